// round 2
// baseline (speedup 1.0000x reference)
#include <cuda_runtime.h>

// 2-layer LSTM (B=2048, T=1024, I=6, H=38) + final projection (C=8), fp32.
// Persistent blocks: each block owns 8 batch rows for the whole time loop.
// Thread = (batch-pair, padded hidden unit). Gate-pair packed f32x2 FMAs:
//   acc_if = {gate_i, gate_f}, acc_go = {gate_g, gate_o} per batch.
//   weight operand: LDS.128 -> {wi,wf},{wg,wo}  (two natural u64 halves)
//   h operand: h stored DUPLICATED in smem -> LDS.128 {h0,h0,h1,h1}
// Inner iteration: 2x LDS.128 + 4x fma.rn.f32x2 = 6 instr / 8 MACs.

namespace {
constexpr int Bsz = 2048, Tt = 1024, NI = 6, H = 38, HP = 40, Cc = 8;
constexpr int BT = 8;             // batches per block
constexpr int K0 = NI + HP;       // 46 : [x(6) ; h0(40)]
constexpr int K1 = HP + HP;       // 80 : [h0(40) ; h1(40)]
constexpr int NPAIR = BT / 2;     // 4 batch-pairs
constexpr int NTHR = NPAIR * HP;  // 160 threads
constexpr int W0N = K0 * HP * 4;  // 7360 floats
constexpr int W1N = K1 * HP * 4;  // 12800 floats
constexpr int S0N = K0 * BT * 2;  // duplicated state rows, 736 floats
constexpr int S1N = K1 * BT * 2;  // 1280 floats
constexpr int SMEM_FLOATS = W0N + W1N + S0N + S1N;  // 22176 -> 88704 B
}

typedef unsigned long long ull;

__device__ __forceinline__ ull pk2(float a, float b) {
    ull r; asm("mov.b64 %0, {%1, %2};" : "=l"(r) : "f"(a), "f"(b)); return r;
}
__device__ __forceinline__ void fma2(ull &d, ull a, ull b) {
    asm("fma.rn.f32x2 %0, %1, %2, %0;" : "+l"(d) : "l"(a), "l"(b));
}
__device__ __forceinline__ void unpk2(ull v, float &a, float &b) {
    asm("mov.b64 {%0, %1}, %2;" : "=f"(a), "=f"(b) : "l"(v));
}
__device__ __forceinline__ float sigm(float x) {
    return __fdividef(1.0f, 1.0f + __expf(-x));
}
__device__ __forceinline__ float tanh_(float x) {
    // 2/(1+e^{-2x}) - 1 : saturates cleanly to +-1, no NaN at extremes
    return __fdividef(2.0f, 1.0f + __expf(-2.0f * x)) - 1.0f;
}

__global__ void __launch_bounds__(NTHR, 2) lstm_kernel(
    const float* __restrict__ x,    const float* __restrict__ Wih0,
    const float* __restrict__ Whh0, const float* __restrict__ b0,
    const float* __restrict__ Wih1, const float* __restrict__ Whh1,
    const float* __restrict__ b1,   const float* __restrict__ Wc,
    const float* __restrict__ bc,   float* __restrict__ out)
{
    extern __shared__ float sm[];
    float* W0s = sm;            // [k][q][4] = rows {q, H+q, 2H+q, 3H+q} of cat weights
    float* W1s = W0s + W0N;
    float* s0d = W1s + W1N;     // [k][b][2] duplicated state, k in [0,K0)
    float* s1d = s0d + S0N;     // [k][b][2],                 k in [0,K1)

    const int px = threadIdx.x;            // batch pair 0..3
    const int q  = threadIdx.y;            // padded unit 0..39
    const int tid = px + NPAIR * q;
    const int bb0 = blockIdx.x * BT + 2 * px;

    // ---- stage weights into smem (zero-padded to HP units) ----
    for (int idx = tid; idx < W0N; idx += NTHR) {
        int g = idx & 3, qq = (idx >> 2) % HP, k = idx / (4 * HP);
        float v = 0.0f;
        if (qq < H) {
            int row = g * H + qq;
            if (k < NI)             v = Wih0[row * NI + k];
            else if (k - NI < H)    v = Whh0[row * H + (k - NI)];
        }
        W0s[idx] = v;
    }
    for (int idx = tid; idx < W1N; idx += NTHR) {
        int g = idx & 3, qq = (idx >> 2) % HP, k = idx / (4 * HP);
        float v = 0.0f;
        if (qq < H) {
            int row = g * H + qq;
            if (k < HP) { if (k < H) v = Wih1[row * H + k]; }
            else        { int kk = k - HP; if (kk < H) v = Whh1[row * H + kk]; }
        }
        W1s[idx] = v;
    }
    for (int idx = tid; idx < S0N; idx += NTHR) s0d[idx] = 0.0f;
    for (int idx = tid; idx < S1N; idx += NTHR) s1d[idx] = 0.0f;

    // ---- per-thread packed biases ----
    ull bif0, bgo0, bif1, bgo1;
    if (q < H) {
        bif0 = pk2(b0[q], b0[H + q]); bgo0 = pk2(b0[2 * H + q], b0[3 * H + q]);
        bif1 = pk2(b1[q], b1[H + q]); bgo1 = pk2(b1[2 * H + q], b1[3 * H + q]);
    } else {
        bif0 = bgo0 = bif1 = bgo1 = pk2(0.0f, 0.0f);
    }

    // ---- x at t=0 into s0d (duplicated) ----
    if (q < NI) {
        float x0 = x[(size_t)bb0 * Tt * NI + q];
        float x1 = x[(size_t)(bb0 + 1) * Tt * NI + q];
        ulonglong2 xv; xv.x = pk2(x0, x0); xv.y = pk2(x1, x1);
        *(ulonglong2*)(s0d + q * (2 * BT) + 4 * px) = xv;
    }
    __syncthreads();

    float c00 = 0.0f, c01 = 0.0f, c10 = 0.0f, c11 = 0.0f;

    const float* hb0 = s0d + 4 * px;
    const float* hb1 = s1d + 4 * px;
    const float* wq0 = W0s + 4 * q;
    const float* wq1 = W1s + 4 * q;

    for (int t = 0; t < Tt; ++t) {
        // prefetch x_{t+1}
        float xp0 = 0.0f, xp1 = 0.0f;
        if (q < NI && t + 1 < Tt) {
            xp0 = x[(size_t)bb0 * Tt * NI + (t + 1) * NI + q];
            xp1 = x[(size_t)(bb0 + 1) * Tt * NI + (t + 1) * NI + q];
        }

        // ================= layer 0 =================
        float h00, h01;
        {
            ull aif_b0 = bif0, aif_b1 = bif0, ago_b0 = bgo0, ago_b1 = bgo0;
            #pragma unroll
            for (int k = 0; k < K0; ++k) {
                ulonglong2 h2 = *(const ulonglong2*)(hb0 + k * (2 * BT));
                ulonglong2 w2 = *(const ulonglong2*)(wq0 + k * (4 * HP));
                fma2(aif_b0, h2.x, w2.x);
                fma2(aif_b1, h2.y, w2.x);
                fma2(ago_b0, h2.x, w2.y);
                fma2(ago_b1, h2.y, w2.y);
            }
            float gi0, gf0, gg0, go0, gi1, gf1, gg1, go1;
            unpk2(aif_b0, gi0, gf0); unpk2(ago_b0, gg0, go0);
            unpk2(aif_b1, gi1, gf1); unpk2(ago_b1, gg1, go1);
            float i0 = sigm(gi0), f0 = sigm(gf0), g0 = tanh_(gg0), o0 = sigm(go0);
            c00 = f0 * c00 + i0 * g0;
            h00 = o0 * tanh_(c00);
            float i1 = sigm(gi1), f1 = sigm(gf1), g1 = tanh_(gg1), o1 = sigm(go1);
            c01 = f1 * c01 + i1 * g1;
            h01 = o1 * tanh_(c01);
        }

        __syncthreads();   // all layer-0 reads of s0d complete
        {
            ulonglong2 hv; hv.x = pk2(h00, h00); hv.y = pk2(h01, h01);
            *(ulonglong2*)(s0d + (NI + q) * (2 * BT) + 4 * px) = hv;  // for next step's layer 0
            *(ulonglong2*)(s1d + q * (2 * BT) + 4 * px) = hv;         // for this step's layer 1
            if (q < NI && t + 1 < Tt) {
                ulonglong2 xv; xv.x = pk2(xp0, xp0); xv.y = pk2(xp1, xp1);
                *(ulonglong2*)(s0d + q * (2 * BT) + 4 * px) = xv;
            }
        }
        __syncthreads();   // writes visible

        // ================= layer 1 =================
        float h10, h11;
        {
            ull aif_b0 = bif1, aif_b1 = bif1, ago_b0 = bgo1, ago_b1 = bgo1;
            #pragma unroll
            for (int k = 0; k < K1; ++k) {
                ulonglong2 h2 = *(const ulonglong2*)(hb1 + k * (2 * BT));
                ulonglong2 w2 = *(const ulonglong2*)(wq1 + k * (4 * HP));
                fma2(aif_b0, h2.x, w2.x);
                fma2(aif_b1, h2.y, w2.x);
                fma2(ago_b0, h2.x, w2.y);
                fma2(ago_b1, h2.y, w2.y);
            }
            float gi0, gf0, gg0, go0, gi1, gf1, gg1, go1;
            unpk2(aif_b0, gi0, gf0); unpk2(ago_b0, gg0, go0);
            unpk2(aif_b1, gi1, gf1); unpk2(ago_b1, gg1, go1);
            float i0 = sigm(gi0), f0 = sigm(gf0), g0 = tanh_(gg0), o0 = sigm(go0);
            c10 = f0 * c10 + i0 * g0;
            h10 = o0 * tanh_(c10);
            float i1 = sigm(gi1), f1 = sigm(gf1), g1 = tanh_(gg1), o1 = sigm(go1);
            c11 = f1 * c11 + i1 * g1;
            h11 = o1 * tanh_(c11);
        }

        __syncthreads();   // all layer-1 reads of s1d complete
        {
            ulonglong2 hv; hv.x = pk2(h10, h10); hv.y = pk2(h11, h11);
            *(ulonglong2*)(s1d + (HP + q) * (2 * BT) + 4 * px) = hv;
        }
        // h1 writes are consumed only after the next step's two barriers
    }
    __syncthreads();

    // ---- final projection: out[b][c] = bc[c] + sum_k Wc[c][k] * h1_last[b][k] ----
    if (q < Cc) {
        float a0 = bc[q], a1 = bc[q];
        #pragma unroll
        for (int k = 0; k < H; ++k) {
            float w = Wc[q * H + k];
            a0 += w * s1d[(HP + k) * (2 * BT) + 4 * px];
            a1 += w * s1d[(HP + k) * (2 * BT) + 4 * px + 2];
        }
        out[(size_t)bb0 * Cc + q] = a0;
        out[(size_t)(bb0 + 1) * Cc + q] = a1;
    }
}

extern "C" void kernel_launch(void* const* d_in, const int* in_sizes, int n_in,
                              void* d_out, int out_size) {
    const float* x    = (const float*)d_in[0];
    const float* Wih0 = (const float*)d_in[1];
    const float* Whh0 = (const float*)d_in[2];
    const float* b0   = (const float*)d_in[3];
    const float* Wih1 = (const float*)d_in[4];
    const float* Whh1 = (const float*)d_in[5];
    const float* b1   = (const float*)d_in[6];
    const float* Wc   = (const float*)d_in[7];
    const float* bc   = (const float*)d_in[8];

    const int smem_bytes = SMEM_FLOATS * (int)sizeof(float);
    cudaFuncSetAttribute(lstm_kernel, cudaFuncAttributeMaxDynamicSharedMemorySize, smem_bytes);
    lstm_kernel<<<Bsz / BT, dim3(NPAIR, HP, 1), smem_bytes>>>(
        x, Wih0, Whh0, b0, Wih1, Whh1, b1, Wc, bc, (float*)d_out);
}

// round 3
// speedup vs baseline: 1.0021x; 1.0021x over previous
#include <cuda_runtime.h>

// 2-layer LSTM (B=2048, T=1024, I=6, H=38) + final projection (C=8), fp32.
// Persistent blocks: each block owns 8 batch rows for the whole time loop.
// Thread = (batch-pair, padded hidden unit). Gate-pair packed f32x2 FMAs:
//   acc_if = {gate_i, gate_f}, acc_go = {gate_g, gate_o} per batch.
//   weight operand: LDS.128 -> {wi,wf},{wg,wo}  (two natural u64 halves)
//   h operand: h stored DUPLICATED in smem -> LDS.128 {h0,h0,h1,h1}
// Inner iteration: 2x LDS.128 + 4x fma.rn.f32x2 = 6 instr / 8 MACs.

namespace {
constexpr int Bsz = 2048, Tt = 1024, NI = 6, H = 38, HP = 40, Cc = 8;
constexpr int BT = 8;             // batches per block
constexpr int K0 = NI + HP;       // 46 : [x(6) ; h0(40)]
constexpr int K1 = HP + HP;       // 80 : [h0(40) ; h1(40)]
constexpr int NPAIR = BT / 2;     // 4 batch-pairs
constexpr int NTHR = NPAIR * HP;  // 160 threads
constexpr int W0N = K0 * HP * 4;  // 7360 floats
constexpr int W1N = K1 * HP * 4;  // 12800 floats
constexpr int S0N = K0 * BT * 2;  // duplicated state rows, 736 floats
constexpr int S1N = K1 * BT * 2;  // 1280 floats
constexpr int SMEM_FLOATS = W0N + W1N + S0N + S1N;  // 22176 -> 88704 B
}

typedef unsigned long long ull;

__device__ __forceinline__ ull pk2(float a, float b) {
    ull r; asm("mov.b64 %0, {%1, %2};" : "=l"(r) : "f"(a), "f"(b)); return r;
}
__device__ __forceinline__ void fma2(ull &d, ull a, ull b) {
    asm("fma.rn.f32x2 %0, %1, %2, %0;" : "+l"(d) : "l"(a), "l"(b));
}
__device__ __forceinline__ void unpk2(ull v, float &a, float &b) {
    asm("mov.b64 {%0, %1}, %2;" : "=f"(a), "=f"(b) : "l"(v));
}
__device__ __forceinline__ float sigm(float x) {
    return __fdividef(1.0f, 1.0f + __expf(-x));
}
__device__ __forceinline__ float tanh_(float x) {
    // 2/(1+e^{-2x}) - 1 : saturates cleanly to +-1, no NaN at extremes
    return __fdividef(2.0f, 1.0f + __expf(-2.0f * x)) - 1.0f;
}

__global__ void __launch_bounds__(NTHR, 2) lstm_kernel(
    const float* __restrict__ x,    const float* __restrict__ Wih0,
    const float* __restrict__ Whh0, const float* __restrict__ b0,
    const float* __restrict__ Wih1, const float* __restrict__ Whh1,
    const float* __restrict__ b1,   const float* __restrict__ Wc,
    const float* __restrict__ bc,   float* __restrict__ out)
{
    extern __shared__ float sm[];
    float* W0s = sm;            // [k][q][4] = rows {q, H+q, 2H+q, 3H+q} of cat weights
    float* W1s = W0s + W0N;
    float* s0d = W1s + W1N;     // [k][b][2] duplicated state, k in [0,K0)
    float* s1d = s0d + S0N;     // [k][b][2],                 k in [0,K1)

    const int px = threadIdx.x;            // batch pair 0..3
    const int q  = threadIdx.y;            // padded unit 0..39
    const int tid = px + NPAIR * q;
    const int bb0 = blockIdx.x * BT + 2 * px;

    // ---- stage weights into smem (zero-padded to HP units) ----
    for (int idx = tid; idx < W0N; idx += NTHR) {
        int g = idx & 3, qq = (idx >> 2) % HP, k = idx / (4 * HP);
        float v = 0.0f;
        if (qq < H) {
            int row = g * H + qq;
            if (k < NI)             v = Wih0[row * NI + k];
            else if (k - NI < H)    v = Whh0[row * H + (k - NI)];
        }
        W0s[idx] = v;
    }
    for (int idx = tid; idx < W1N; idx += NTHR) {
        int g = idx & 3, qq = (idx >> 2) % HP, k = idx / (4 * HP);
        float v = 0.0f;
        if (qq < H) {
            int row = g * H + qq;
            if (k < HP) { if (k < H) v = Wih1[row * H + k]; }
            else        { int kk = k - HP; if (kk < H) v = Whh1[row * H + kk]; }
        }
        W1s[idx] = v;
    }
    for (int idx = tid; idx < S0N; idx += NTHR) s0d[idx] = 0.0f;
    for (int idx = tid; idx < S1N; idx += NTHR) s1d[idx] = 0.0f;

    // ---- per-thread packed biases ----
    ull bif0, bgo0, bif1, bgo1;
    if (q < H) {
        bif0 = pk2(b0[q], b0[H + q]); bgo0 = pk2(b0[2 * H + q], b0[3 * H + q]);
        bif1 = pk2(b1[q], b1[H + q]); bgo1 = pk2(b1[2 * H + q], b1[3 * H + q]);
    } else {
        bif0 = bgo0 = bif1 = bgo1 = pk2(0.0f, 0.0f);
    }

    // ---- x at t=0 into s0d (duplicated) ----
    if (q < NI) {
        float x0 = x[(size_t)bb0 * Tt * NI + q];
        float x1 = x[(size_t)(bb0 + 1) * Tt * NI + q];
        ulonglong2 xv; xv.x = pk2(x0, x0); xv.y = pk2(x1, x1);
        *(ulonglong2*)(s0d + q * (2 * BT) + 4 * px) = xv;
    }
    __syncthreads();

    float c00 = 0.0f, c01 = 0.0f, c10 = 0.0f, c11 = 0.0f;

    const float* hb0 = s0d + 4 * px;
    const float* hb1 = s1d + 4 * px;
    const float* wq0 = W0s + 4 * q;
    const float* wq1 = W1s + 4 * q;

    for (int t = 0; t < Tt; ++t) {
        // prefetch x_{t+1}
        float xp0 = 0.0f, xp1 = 0.0f;
        if (q < NI && t + 1 < Tt) {
            xp0 = x[(size_t)bb0 * Tt * NI + (t + 1) * NI + q];
            xp1 = x[(size_t)(bb0 + 1) * Tt * NI + (t + 1) * NI + q];
        }

        // ================= layer 0 =================
        float h00, h01;
        {
            ull aif_b0 = bif0, aif_b1 = bif0, ago_b0 = bgo0, ago_b1 = bgo0;
            #pragma unroll
            for (int k = 0; k < K0; ++k) {
                ulonglong2 h2 = *(const ulonglong2*)(hb0 + k * (2 * BT));
                ulonglong2 w2 = *(const ulonglong2*)(wq0 + k * (4 * HP));
                fma2(aif_b0, h2.x, w2.x);
                fma2(aif_b1, h2.y, w2.x);
                fma2(ago_b0, h2.x, w2.y);
                fma2(ago_b1, h2.y, w2.y);
            }
            float gi0, gf0, gg0, go0, gi1, gf1, gg1, go1;
            unpk2(aif_b0, gi0, gf0); unpk2(ago_b0, gg0, go0);
            unpk2(aif_b1, gi1, gf1); unpk2(ago_b1, gg1, go1);
            float i0 = sigm(gi0), f0 = sigm(gf0), g0 = tanh_(gg0), o0 = sigm(go0);
            c00 = f0 * c00 + i0 * g0;
            h00 = o0 * tanh_(c00);
            float i1 = sigm(gi1), f1 = sigm(gf1), g1 = tanh_(gg1), o1 = sigm(go1);
            c01 = f1 * c01 + i1 * g1;
            h01 = o1 * tanh_(c01);
        }

        __syncthreads();   // all layer-0 reads of s0d complete
        {
            ulonglong2 hv; hv.x = pk2(h00, h00); hv.y = pk2(h01, h01);
            *(ulonglong2*)(s0d + (NI + q) * (2 * BT) + 4 * px) = hv;  // for next step's layer 0
            *(ulonglong2*)(s1d + q * (2 * BT) + 4 * px) = hv;         // for this step's layer 1
            if (q < NI && t + 1 < Tt) {
                ulonglong2 xv; xv.x = pk2(xp0, xp0); xv.y = pk2(xp1, xp1);
                *(ulonglong2*)(s0d + q * (2 * BT) + 4 * px) = xv;
            }
        }
        __syncthreads();   // writes visible

        // ================= layer 1 =================
        float h10, h11;
        {
            ull aif_b0 = bif1, aif_b1 = bif1, ago_b0 = bgo1, ago_b1 = bgo1;
            #pragma unroll
            for (int k = 0; k < K1; ++k) {
                ulonglong2 h2 = *(const ulonglong2*)(hb1 + k * (2 * BT));
                ulonglong2 w2 = *(const ulonglong2*)(wq1 + k * (4 * HP));
                fma2(aif_b0, h2.x, w2.x);
                fma2(aif_b1, h2.y, w2.x);
                fma2(ago_b0, h2.x, w2.y);
                fma2(ago_b1, h2.y, w2.y);
            }
            float gi0, gf0, gg0, go0, gi1, gf1, gg1, go1;
            unpk2(aif_b0, gi0, gf0); unpk2(ago_b0, gg0, go0);
            unpk2(aif_b1, gi1, gf1); unpk2(ago_b1, gg1, go1);
            float i0 = sigm(gi0), f0 = sigm(gf0), g0 = tanh_(gg0), o0 = sigm(go0);
            c10 = f0 * c10 + i0 * g0;
            h10 = o0 * tanh_(c10);
            float i1 = sigm(gi1), f1 = sigm(gf1), g1 = tanh_(gg1), o1 = sigm(go1);
            c11 = f1 * c11 + i1 * g1;
            h11 = o1 * tanh_(c11);
        }

        __syncthreads();   // all layer-1 reads of s1d complete
        {
            ulonglong2 hv; hv.x = pk2(h10, h10); hv.y = pk2(h11, h11);
            *(ulonglong2*)(s1d + (HP + q) * (2 * BT) + 4 * px) = hv;
        }
        // h1 writes are consumed only after the next step's two barriers
    }
    __syncthreads();

    // ---- final projection: out[b][c] = bc[c] + sum_k Wc[c][k] * h1_last[b][k] ----
    if (q < Cc) {
        float a0 = bc[q], a1 = bc[q];
        #pragma unroll
        for (int k = 0; k < H; ++k) {
            float w = Wc[q * H + k];
            a0 += w * s1d[(HP + k) * (2 * BT) + 4 * px];
            a1 += w * s1d[(HP + k) * (2 * BT) + 4 * px + 2];
        }
        out[(size_t)bb0 * Cc + q] = a0;
        out[(size_t)(bb0 + 1) * Cc + q] = a1;
    }
}

extern "C" void kernel_launch(void* const* d_in, const int* in_sizes, int n_in,
                              void* d_out, int out_size) {
    const float* x    = (const float*)d_in[0];
    const float* Wih0 = (const float*)d_in[1];
    const float* Whh0 = (const float*)d_in[2];
    const float* b0   = (const float*)d_in[3];
    const float* Wih1 = (const float*)d_in[4];
    const float* Whh1 = (const float*)d_in[5];
    const float* b1   = (const float*)d_in[6];
    const float* Wc   = (const float*)d_in[7];
    const float* bc   = (const float*)d_in[8];

    const int smem_bytes = SMEM_FLOATS * (int)sizeof(float);
    cudaFuncSetAttribute(lstm_kernel, cudaFuncAttributeMaxDynamicSharedMemorySize, smem_bytes);
    lstm_kernel<<<Bsz / BT, dim3(NPAIR, HP, 1), smem_bytes>>>(
        x, Wih0, Whh0, b0, Wih1, Whh1, b1, Wc, bc, (float*)d_out);
}

// round 4
// speedup vs baseline: 1.0034x; 1.0013x over previous
#include <cuda_runtime.h>

// 2-layer LSTM (B=2048, T=1024, I=6, H=38) + final projection (C=8), fp32.
// Persistent blocks: each block owns 8 batch rows for the whole time loop.
// Thread = (batch-pair, padded hidden unit). Gate-pair packed f32x2 FMAs:
//   acc_if = {gate_i, gate_f}, acc_go = {gate_g, gate_o} per batch.
//   weight operand: LDS.128 -> {wi,wf},{wg,wo}  (two natural u64 halves)
//   h operand: h stored DUPLICATED in smem -> LDS.128 {h0,h0,h1,h1}
// Inner iteration: 2x LDS.128 + 4x fma.rn.f32x2 = 6 instr / 8 MACs.

namespace {
constexpr int Bsz = 2048, Tt = 1024, NI = 6, H = 38, HP = 40, Cc = 8;
constexpr int BT = 8;             // batches per block
constexpr int K0 = NI + HP;       // 46 : [x(6) ; h0(40)]
constexpr int K1 = HP + HP;       // 80 : [h0(40) ; h1(40)]
constexpr int NPAIR = BT / 2;     // 4 batch-pairs
constexpr int NTHR = NPAIR * HP;  // 160 threads
constexpr int W0N = K0 * HP * 4;  // 7360 floats
constexpr int W1N = K1 * HP * 4;  // 12800 floats
constexpr int S0N = K0 * BT * 2;  // duplicated state rows, 736 floats
constexpr int S1N = K1 * BT * 2;  // 1280 floats
constexpr int SMEM_FLOATS = W0N + W1N + S0N + S1N;  // 22176 -> 88704 B
}

typedef unsigned long long ull;

__device__ __forceinline__ ull pk2(float a, float b) {
    ull r; asm("mov.b64 %0, {%1, %2};" : "=l"(r) : "f"(a), "f"(b)); return r;
}
__device__ __forceinline__ void fma2(ull &d, ull a, ull b) {
    asm("fma.rn.f32x2 %0, %1, %2, %0;" : "+l"(d) : "l"(a), "l"(b));
}
__device__ __forceinline__ void unpk2(ull v, float &a, float &b) {
    asm("mov.b64 {%0, %1}, %2;" : "=f"(a), "=f"(b) : "l"(v));
}
__device__ __forceinline__ float sigm(float x) {
    return __fdividef(1.0f, 1.0f + __expf(-x));
}
__device__ __forceinline__ float tanh_(float x) {
    // 2/(1+e^{-2x}) - 1 : saturates cleanly to +-1, no NaN at extremes
    return __fdividef(2.0f, 1.0f + __expf(-2.0f * x)) - 1.0f;
}

__global__ void __launch_bounds__(NTHR, 2) lstm_kernel(
    const float* __restrict__ x,    const float* __restrict__ Wih0,
    const float* __restrict__ Whh0, const float* __restrict__ b0,
    const float* __restrict__ Wih1, const float* __restrict__ Whh1,
    const float* __restrict__ b1,   const float* __restrict__ Wc,
    const float* __restrict__ bc,   float* __restrict__ out)
{
    extern __shared__ float sm[];
    float* W0s = sm;            // [k][q][4] = rows {q, H+q, 2H+q, 3H+q} of cat weights
    float* W1s = W0s + W0N;
    float* s0d = W1s + W1N;     // [k][b][2] duplicated state, k in [0,K0)
    float* s1d = s0d + S0N;     // [k][b][2],                 k in [0,K1)

    const int px = threadIdx.x;            // batch pair 0..3
    const int q  = threadIdx.y;            // padded unit 0..39
    const int tid = px + NPAIR * q;
    const int bb0 = blockIdx.x * BT + 2 * px;

    // ---- stage weights into smem (zero-padded to HP units) ----
    for (int idx = tid; idx < W0N; idx += NTHR) {
        int g = idx & 3, qq = (idx >> 2) % HP, k = idx / (4 * HP);
        float v = 0.0f;
        if (qq < H) {
            int row = g * H + qq;
            if (k < NI)             v = Wih0[row * NI + k];
            else if (k - NI < H)    v = Whh0[row * H + (k - NI)];
        }
        W0s[idx] = v;
    }
    for (int idx = tid; idx < W1N; idx += NTHR) {
        int g = idx & 3, qq = (idx >> 2) % HP, k = idx / (4 * HP);
        float v = 0.0f;
        if (qq < H) {
            int row = g * H + qq;
            if (k < HP) { if (k < H) v = Wih1[row * H + k]; }
            else        { int kk = k - HP; if (kk < H) v = Whh1[row * H + kk]; }
        }
        W1s[idx] = v;
    }
    for (int idx = tid; idx < S0N; idx += NTHR) s0d[idx] = 0.0f;
    for (int idx = tid; idx < S1N; idx += NTHR) s1d[idx] = 0.0f;

    // ---- per-thread packed biases ----
    ull bif0, bgo0, bif1, bgo1;
    if (q < H) {
        bif0 = pk2(b0[q], b0[H + q]); bgo0 = pk2(b0[2 * H + q], b0[3 * H + q]);
        bif1 = pk2(b1[q], b1[H + q]); bgo1 = pk2(b1[2 * H + q], b1[3 * H + q]);
    } else {
        bif0 = bgo0 = bif1 = bgo1 = pk2(0.0f, 0.0f);
    }

    // ---- x at t=0 into s0d (duplicated) ----
    if (q < NI) {
        float x0 = x[(size_t)bb0 * Tt * NI + q];
        float x1 = x[(size_t)(bb0 + 1) * Tt * NI + q];
        ulonglong2 xv; xv.x = pk2(x0, x0); xv.y = pk2(x1, x1);
        *(ulonglong2*)(s0d + q * (2 * BT) + 4 * px) = xv;
    }
    __syncthreads();

    float c00 = 0.0f, c01 = 0.0f, c10 = 0.0f, c11 = 0.0f;

    const float* hb0 = s0d + 4 * px;
    const float* hb1 = s1d + 4 * px;
    const float* wq0 = W0s + 4 * q;
    const float* wq1 = W1s + 4 * q;

    for (int t = 0; t < Tt; ++t) {
        // prefetch x_{t+1}
        float xp0 = 0.0f, xp1 = 0.0f;
        if (q < NI && t + 1 < Tt) {
            xp0 = x[(size_t)bb0 * Tt * NI + (t + 1) * NI + q];
            xp1 = x[(size_t)(bb0 + 1) * Tt * NI + (t + 1) * NI + q];
        }

        // ================= layer 0 =================
        float h00, h01;
        {
            ull aif_b0 = bif0, aif_b1 = bif0, ago_b0 = bgo0, ago_b1 = bgo0;
            #pragma unroll
            for (int k = 0; k < K0; ++k) {
                ulonglong2 h2 = *(const ulonglong2*)(hb0 + k * (2 * BT));
                ulonglong2 w2 = *(const ulonglong2*)(wq0 + k * (4 * HP));
                fma2(aif_b0, h2.x, w2.x);
                fma2(aif_b1, h2.y, w2.x);
                fma2(ago_b0, h2.x, w2.y);
                fma2(ago_b1, h2.y, w2.y);
            }
            float gi0, gf0, gg0, go0, gi1, gf1, gg1, go1;
            unpk2(aif_b0, gi0, gf0); unpk2(ago_b0, gg0, go0);
            unpk2(aif_b1, gi1, gf1); unpk2(ago_b1, gg1, go1);
            float i0 = sigm(gi0), f0 = sigm(gf0), g0 = tanh_(gg0), o0 = sigm(go0);
            c00 = f0 * c00 + i0 * g0;
            h00 = o0 * tanh_(c00);
            float i1 = sigm(gi1), f1 = sigm(gf1), g1 = tanh_(gg1), o1 = sigm(go1);
            c01 = f1 * c01 + i1 * g1;
            h01 = o1 * tanh_(c01);
        }

        __syncthreads();   // all layer-0 reads of s0d complete
        {
            ulonglong2 hv; hv.x = pk2(h00, h00); hv.y = pk2(h01, h01);
            *(ulonglong2*)(s0d + (NI + q) * (2 * BT) + 4 * px) = hv;  // for next step's layer 0
            *(ulonglong2*)(s1d + q * (2 * BT) + 4 * px) = hv;         // for this step's layer 1
            if (q < NI && t + 1 < Tt) {
                ulonglong2 xv; xv.x = pk2(xp0, xp0); xv.y = pk2(xp1, xp1);
                *(ulonglong2*)(s0d + q * (2 * BT) + 4 * px) = xv;
            }
        }
        __syncthreads();   // writes visible

        // ================= layer 1 =================
        float h10, h11;
        {
            ull aif_b0 = bif1, aif_b1 = bif1, ago_b0 = bgo1, ago_b1 = bgo1;
            #pragma unroll
            for (int k = 0; k < K1; ++k) {
                ulonglong2 h2 = *(const ulonglong2*)(hb1 + k * (2 * BT));
                ulonglong2 w2 = *(const ulonglong2*)(wq1 + k * (4 * HP));
                fma2(aif_b0, h2.x, w2.x);
                fma2(aif_b1, h2.y, w2.x);
                fma2(ago_b0, h2.x, w2.y);
                fma2(ago_b1, h2.y, w2.y);
            }
            float gi0, gf0, gg0, go0, gi1, gf1, gg1, go1;
            unpk2(aif_b0, gi0, gf0); unpk2(ago_b0, gg0, go0);
            unpk2(aif_b1, gi1, gf1); unpk2(ago_b1, gg1, go1);
            float i0 = sigm(gi0), f0 = sigm(gf0), g0 = tanh_(gg0), o0 = sigm(go0);
            c10 = f0 * c10 + i0 * g0;
            h10 = o0 * tanh_(c10);
            float i1 = sigm(gi1), f1 = sigm(gf1), g1 = tanh_(gg1), o1 = sigm(go1);
            c11 = f1 * c11 + i1 * g1;
            h11 = o1 * tanh_(c11);
        }

        __syncthreads();   // all layer-1 reads of s1d complete
        {
            ulonglong2 hv; hv.x = pk2(h10, h10); hv.y = pk2(h11, h11);
            *(ulonglong2*)(s1d + (HP + q) * (2 * BT) + 4 * px) = hv;
        }
        // h1 writes are consumed only after the next step's two barriers
    }
    __syncthreads();

    // ---- final projection: out[b][c] = bc[c] + sum_k Wc[c][k] * h1_last[b][k] ----
    if (q < Cc) {
        float a0 = bc[q], a1 = bc[q];
        #pragma unroll
        for (int k = 0; k < H; ++k) {
            float w = Wc[q * H + k];
            a0 += w * s1d[(HP + k) * (2 * BT) + 4 * px];
            a1 += w * s1d[(HP + k) * (2 * BT) + 4 * px + 2];
        }
        out[(size_t)bb0 * Cc + q] = a0;
        out[(size_t)(bb0 + 1) * Cc + q] = a1;
    }
}

extern "C" void kernel_launch(void* const* d_in, const int* in_sizes, int n_in,
                              void* d_out, int out_size) {
    const float* x    = (const float*)d_in[0];
    const float* Wih0 = (const float*)d_in[1];
    const float* Whh0 = (const float*)d_in[2];
    const float* b0   = (const float*)d_in[3];
    const float* Wih1 = (const float*)d_in[4];
    const float* Whh1 = (const float*)d_in[5];
    const float* b1   = (const float*)d_in[6];
    const float* Wc   = (const float*)d_in[7];
    const float* bc   = (const float*)d_in[8];

    const int smem_bytes = SMEM_FLOATS * (int)sizeof(float);
    cudaFuncSetAttribute(lstm_kernel, cudaFuncAttributeMaxDynamicSharedMemorySize, smem_bytes);
    lstm_kernel<<<Bsz / BT, dim3(NPAIR, HP, 1), smem_bytes>>>(
        x, Wih0, Whh0, b0, Wih1, Whh1, b1, Wc, bc, (float*)d_out);
}